// round 16
// baseline (speedup 1.0000x reference)
#include <cuda_runtime.h>
#include <cuda_bf16.h>
#include <cuda_fp16.h>
#include <math.h>

// Problem-size maxima (compile-time buffer sizing; runtime sizes passed as args)
#define NMAX 100000
#define EMAX 1600000
#define H 64

// ---------------------------------------------------------------------------
// Device scratch (allocation-free rule: __device__ globals)
// ---------------------------------------------------------------------------
__device__ __align__(16) float g_bufA[NMAX * H];   // 25.6 MB (hw1 half2; PrH half2)
__device__ __align__(16) float g_bufB[NMAX * H];   // 25.6 MB (hw2 half2; PcH half2)
__device__ int   g_cnt [NMAX];
__device__ int   g_fill[NMAX];
__device__ int   g_ptr [NMAX];
__device__ int   g_srow[EMAX];                     // 6.4 MB (CSR source row)
__device__ float g_wrow[EMAX];                     // 6.4 MB (pre-gathered dinv[row])
__device__ int   g_eid [EMAX];                     // 6.4 MB (original edge index)
__device__ float g_dinv[NMAX];
__device__ int   g_bsum[256];
__device__ int   g_boff[256];
__device__ __align__(16) float g_ep_s[H], g_ep_t[H];

// ---------------------------------------------------------------------------
// Small setup kernels (side stream)
// ---------------------------------------------------------------------------
__global__ void zero_kernel(int* cnt, int* fill, int n) {
    int i = blockIdx.x * blockDim.x + threadIdx.x;
    if (i < n) { cnt[i] = 0; fill[i] = 0; }
}

// Fold edge-predictor BN (+ ep1 bias) into per-channel scale/shift.
__global__ void prep_consts(const float* __restrict__ ep1_b, const float* __restrict__ ep_g,
                            const float* __restrict__ ep_beta, const float* __restrict__ ep_mean,
                            const float* __restrict__ ep_var,
                            float* ep_s, float* ep_t) {
    int j = threadIdx.x;
    if (j < H) {
        float sp = ep_g[j] * rsqrtf(ep_var[j] + 1e-5f);
        ep_s[j] = sp;
        ep_t[j] = (ep1_b[j] - ep_mean[j]) * sp + ep_beta[j];
    }
}

__global__ void hist_kernel(const int* __restrict__ col, int* cnt, int e) {
    int i = blockIdx.x * blockDim.x + threadIdx.x;
    if (i < e) atomicAdd(&cnt[col[i]], 1);
}

// ---- 3-phase exclusive scan over cnt[] -> ptr[]  (also emits dinv) ----
__global__ void scan1(const int* __restrict__ cnt, int* ptr, int* bsum,
                      float* __restrict__ dinv, int n) {
    __shared__ int sh[1024];
    int t = threadIdx.x;
    int idx = blockIdx.x * 1024 + t;
    int v = (idx < n) ? cnt[idx] : 0;
    if (idx < n) dinv[idx] = rsqrtf((float)(v + 1));   // +1 = self loop; deg >= 1
    sh[t] = v;
    __syncthreads();
    #pragma unroll
    for (int o = 1; o < 1024; o <<= 1) {
        int x = (t >= o) ? sh[t - o] : 0;
        __syncthreads();
        sh[t] += x;
        __syncthreads();
    }
    if (idx < n) ptr[idx] = sh[t] - v;        // exclusive
    if (t == 1023) bsum[blockIdx.x] = sh[t];  // block total
}

__global__ void scan2(const int* __restrict__ bsum, int* boff, int nb) {
    __shared__ int sh[128];
    int t = threadIdx.x;
    int v = (t < nb) ? bsum[t] : 0;
    sh[t] = v;
    __syncthreads();
    #pragma unroll
    for (int o = 1; o < 128; o <<= 1) {
        int x = (t >= o) ? sh[t - o] : 0;
        __syncthreads();
        sh[t] += x;
        __syncthreads();
    }
    if (t < nb) boff[t] = sh[t] - v;          // exclusive
}

__global__ void scan3(int* ptr, const int* __restrict__ boff, int n) {
    int i = blockIdx.x * blockDim.x + threadIdx.x;
    if (i < n) ptr[i] += boff[i >> 10];
}

// CSR fill: bucket edges by destination node (col); also pre-gather edge
// weight and record the original edge index (for CSR-ordered edge predict).
__global__ void fill_kernel(const int* __restrict__ row, const int* __restrict__ col,
                            const int* __restrict__ ptr, int* fill, int* srow,
                            float* wrow, int* eid,
                            const float* __restrict__ dinv, int e) {
    int i = blockIdx.x * blockDim.x + threadIdx.x;
    if (i >= e) return;
    int c = col[i];
    int r = row[i];
    int pos = ptr[c] + atomicAdd(&fill[c], 1);
    srow[pos] = r;
    wrow[pos] = dinv[r];
    eid[pos]  = i;
}

// ---------------------------------------------------------------------------
// tf32 helpers (3xTF32 split: A*B ~= Ahi*Bhi + Alo*Bhi + Ahi*Blo)
// Staging buffers hold fp32; the hi/lo split happens at fragment load.
// ---------------------------------------------------------------------------
__device__ __forceinline__ unsigned f2tf32(float x) {
    unsigned r;
    asm("cvt.rna.tf32.f32 %0, %1;" : "=r"(r) : "f"(x));
    return r;
}
__device__ __forceinline__ void split_tf32(float x, unsigned& hi, unsigned& lo) {
    hi = f2tf32(x);
    lo = f2tf32(x - __uint_as_float(hi));
}
__device__ __forceinline__ void mma_tf32(float c[4],
                                         unsigned a0, unsigned a1, unsigned a2, unsigned a3,
                                         unsigned b0, unsigned b1) {
    asm volatile("mma.sync.aligned.m16n8k8.row.col.f32.tf32.tf32.f32 "
                 "{%0,%1,%2,%3}, {%4,%5,%6,%7}, {%8,%9}, {%0,%1,%2,%3};"
                 : "+f"(c[0]), "+f"(c[1]), "+f"(c[2]), "+f"(c[3])
                 : "r"(a0), "r"(a1), "r"(a2), "r"(a3), "r"(b0), "r"(b1));
}

#define GTM 128   // rows per block (all node-dim tiles)

// One 16-wide K chunk of the 128x64 tile GEMM (2 kk-steps of m16n8k8).
__device__ __forceinline__ void run_chunk16(const float (*AS)[68], const float (*WS)[20],
                                            int kbase, int rm, int cn, int g, int tt,
                                            float acc[2][4][4]) {
    #pragma unroll
    for (int kk = 0; kk < 16; kk += 8) {
        unsigned ah[2][4], al[2][4];
        #pragma unroll
        for (int mt = 0; mt < 2; mt++) {
            int rb = rm + mt * 16;
            float a0 = AS[rb + g    ][kbase + kk + tt];
            float a1 = AS[rb + g + 8][kbase + kk + tt];
            float a2 = AS[rb + g    ][kbase + kk + tt + 4];
            float a3 = AS[rb + g + 8][kbase + kk + tt + 4];
            split_tf32(a0, ah[mt][0], al[mt][0]);
            split_tf32(a1, ah[mt][1], al[mt][1]);
            split_tf32(a2, ah[mt][2], al[mt][2]);
            split_tf32(a3, ah[mt][3], al[mt][3]);
        }
        #pragma unroll
        for (int nt = 0; nt < 4; nt++) {
            int cb = cn + nt * 8;
            float b0 = WS[cb + g][kk + tt];
            float b1 = WS[cb + g][kk + tt + 4];
            unsigned bh0, bl0, bh1, bl1;
            split_tf32(b0, bh0, bl0);
            split_tf32(b1, bh1, bl1);
            #pragma unroll
            for (int mt = 0; mt < 2; mt++) {
                mma_tf32(acc[mt][nt], ah[mt][0], ah[mt][1], ah[mt][2], ah[mt][3], bh0, bh1);
                mma_tf32(acc[mt][nt], al[mt][0], al[mt][1], al[mt][2], al[mt][3], bh0, bh1);
                mma_tf32(acc[mt][nt], ah[mt][0], ah[mt][1], ah[mt][2], ah[mt][3], bl0, bl1);
            }
        }
    }
}

// ---------------------------------------------------------------------------
// Fused encoder + conv1:  hw1 = half( relu(bn(x@encW + b)) @ conv1W )
// h0 never touches global memory.
// ---------------------------------------------------------------------------
__global__ void __launch_bounds__(256)
fused_enc_conv1(const float* __restrict__ x, const float* __restrict__ encW,
                const float* __restrict__ bn_b, const float* __restrict__ bn_g,
                const float* __restrict__ bn_beta, const float* __restrict__ bn_mean,
                const float* __restrict__ bn_var,
                const float* __restrict__ conv1W,
                __half2* __restrict__ hw1, int M) {
    cudaGridDependencySynchronize();
    __shared__ float wS[64][20];    // W^T chunk (fp32), reused GEMM1+GEMM2
    __shared__ float uS[128][68];   // GEMM1 A-chunks in cols [0..15]; then h0 full

    const int tid  = threadIdx.x;
    const int lane = tid & 31;
    const int warp = tid >> 5;
    const int g = lane >> 2, tt = lane & 3;
    const int rm = (warp >> 1) * 32;
    const int cn = (warp & 1) * 32;
    const int rowBase = blockIdx.x * GTM;

    float acc[2][4][4];
    #pragma unroll
    for (int a = 0; a < 2; a++)
        #pragma unroll
        for (int b = 0; b < 4; b++)
            #pragma unroll
            for (int c = 0; c < 4; c++) acc[a][b][c] = 0.f;

    // ---- GEMM1: x[M,128] @ encW[128,64] ----
    for (int k0 = 0; k0 < 128; k0 += 16) {
        __syncthreads();
        #pragma unroll
        for (int it = 0; it < 2; it++) {
            int li = tid + it * 256;
            int r  = li >> 2;
            int kq = (li & 3) * 4;
            int gr = rowBase + r;
            float4 v = make_float4(0.f, 0.f, 0.f, 0.f);
            if (gr < M) v = *(const float4*)&x[(size_t)gr * 128 + k0 + kq];
            *(float4*)&uS[r][kq] = v;
        }
        {
            int k  = tid >> 4;
            int nq = (tid & 15) * 4;
            float4 v = *(const float4*)&encW[(size_t)(k0 + k) * H + nq];
            wS[nq + 0][k] = v.x; wS[nq + 1][k] = v.y;
            wS[nq + 2][k] = v.z; wS[nq + 3][k] = v.w;
        }
        __syncthreads();
        run_chunk16(uS, wS, 0, rm, cn, g, tt, acc);
    }

    // ---- epilogue 1: BN + ReLU -> h0 into uS (full [128][64]) ----
    __syncthreads();
    #pragma unroll
    for (int nt = 0; nt < 4; nt++) {
        int col = cn + nt * 8 + 2 * tt;
        float s0 = bn_g[col]     * rsqrtf(bn_var[col]     + 1e-5f);
        float s1 = bn_g[col + 1] * rsqrtf(bn_var[col + 1] + 1e-5f);
        float t0 = (bn_b[col]     - bn_mean[col])     * s0 + bn_beta[col];
        float t1 = (bn_b[col + 1] - bn_mean[col + 1]) * s1 + bn_beta[col + 1];
        #pragma unroll
        for (int mt = 0; mt < 2; mt++) {
            int r0 = rm + mt * 16 + g;
            int r1 = r0 + 8;
            *(float2*)&uS[r0][col] = make_float2(
                fmaxf(fmaf(acc[mt][nt][0], s0, t0), 0.f),
                fmaxf(fmaf(acc[mt][nt][1], s1, t1), 0.f));
            *(float2*)&uS[r1][col] = make_float2(
                fmaxf(fmaf(acc[mt][nt][2], s0, t0), 0.f),
                fmaxf(fmaf(acc[mt][nt][3], s1, t1), 0.f));
        }
    }

    // ---- GEMM2: h0[128,64] @ conv1W[64,64] ----
    #pragma unroll
    for (int a = 0; a < 2; a++)
        #pragma unroll
        for (int b = 0; b < 4; b++)
            #pragma unroll
            for (int c = 0; c < 4; c++) acc[a][b][c] = 0.f;

    for (int k0 = 0; k0 < 64; k0 += 16) {
        __syncthreads();
        {
            int k  = tid >> 4;
            int nq = (tid & 15) * 4;
            float4 v = *(const float4*)&conv1W[(size_t)(k0 + k) * H + nq];
            wS[nq + 0][k] = v.x; wS[nq + 1][k] = v.y;
            wS[nq + 2][k] = v.z; wS[nq + 3][k] = v.w;
        }
        __syncthreads();
        run_chunk16(uS, wS, k0, rm, cn, g, tt, acc);
    }

    // ---- epilogue 2: hw1 (packed half2) ----
    #pragma unroll
    for (int nt = 0; nt < 4; nt++) {
        int col = cn + nt * 8 + 2 * tt;
        #pragma unroll
        for (int mt = 0; mt < 2; mt++) {
            int r0 = rowBase + rm + mt * 16 + g;
            int r1 = r0 + 8;
            if (r0 < M) hw1[(size_t)r0 * 32 + (col >> 1)] =
                __floats2half2_rn(acc[mt][nt][0], acc[mt][nt][1]);
            if (r1 < M) hw1[(size_t)r1 * 32 + (col >> 1)] =
                __floats2half2_rn(acc[mt][nt][2], acc[mt][nt][3]);
        }
    }
}

// ---------------------------------------------------------------------------
// fp16 gather helpers
// ---------------------------------------------------------------------------
__device__ __forceinline__ __half2 u2h2(unsigned u) {
    __half2 h; *(unsigned*)&h = u; return h;
}
__device__ __forceinline__ void accH(float* acc, uint4 v, float w) {
    float2 f;
    f = __half22float2(u2h2(v.x)); acc[0] = fmaf(f.x, w, acc[0]); acc[1] = fmaf(f.y, w, acc[1]);
    f = __half22float2(u2h2(v.y)); acc[2] = fmaf(f.x, w, acc[2]); acc[3] = fmaf(f.y, w, acc[3]);
    f = __half22float2(u2h2(v.z)); acc[4] = fmaf(f.x, w, acc[4]); acc[5] = fmaf(f.y, w, acc[5]);
    f = __half22float2(u2h2(v.w)); acc[6] = fmaf(f.x, w, acc[6]); acc[7] = fmaf(f.y, w, acc[7]);
}

// ---------------------------------------------------------------------------
// Fused aggregate(hw1) + conv2:  hw2 = half( relu(Âhw1 + b1) @ conv2W )
// h1 lives only in smem.
// ---------------------------------------------------------------------------
__global__ void __launch_bounds__(256)
fused_agg_conv2(const uint4* __restrict__ hwH4, const int* __restrict__ ptr,
                const int* __restrict__ cnt, const int* __restrict__ srow,
                const float* __restrict__ wrow, const float* __restrict__ dinv,
                const float* __restrict__ bias, const float* __restrict__ conv2W,
                __half2* __restrict__ hw2, int M) {
    cudaGridDependencySynchronize();   // hw1 produced by fused_enc_conv1
    __shared__ float wS[64][20];
    __shared__ float hS[128][68];

    const int tid  = threadIdx.x;
    const int qg = tid >> 3, ql = tid & 7;
    const int rowBase = blockIdx.x * GTM;

    float4 b0 = ((const float4*)bias)[ql * 2];
    float4 b1 = ((const float4*)bias)[ql * 2 + 1];

    // ---- aggregation phase: 32 groups x 4 nodes ----
    #pragma unroll 1
    for (int j = 0; j < 4; j++) {
        int r  = qg * 4 + j;
        int nd = rowBase + r;
        if (nd < M) {
            float dn = dinv[nd];
            int st = ptr[nd], c = cnt[nd];
            float acc[8] = {0.f, 0.f, 0.f, 0.f, 0.f, 0.f, 0.f, 0.f};
            accH(acc, hwH4[(size_t)nd * 8 + ql], dn);      // self loop
            int i = st, iend = st + c;
            for (; i + 4 <= iend; i += 4) {
                int r0 = srow[i], r1 = srow[i + 1], r2 = srow[i + 2], r3 = srow[i + 3];
                float w0 = wrow[i], w1 = wrow[i + 1], w2 = wrow[i + 2], w3 = wrow[i + 3];
                uint4 v0 = hwH4[(size_t)r0 * 8 + ql];
                uint4 v1 = hwH4[(size_t)r1 * 8 + ql];
                uint4 v2 = hwH4[(size_t)r2 * 8 + ql];
                uint4 v3 = hwH4[(size_t)r3 * 8 + ql];
                accH(acc, v0, w0); accH(acc, v1, w1);
                accH(acc, v2, w2); accH(acc, v3, w3);
            }
            for (; i < iend; i++)
                accH(acc, hwH4[(size_t)srow[i] * 8 + ql], wrow[i]);

            float4 o0, o1;
            o0.x = fmaxf(fmaf(acc[0], dn, b0.x), 0.f);
            o0.y = fmaxf(fmaf(acc[1], dn, b0.y), 0.f);
            o0.z = fmaxf(fmaf(acc[2], dn, b0.z), 0.f);
            o0.w = fmaxf(fmaf(acc[3], dn, b0.w), 0.f);
            o1.x = fmaxf(fmaf(acc[4], dn, b1.x), 0.f);
            o1.y = fmaxf(fmaf(acc[5], dn, b1.y), 0.f);
            o1.z = fmaxf(fmaf(acc[6], dn, b1.z), 0.f);
            o1.w = fmaxf(fmaf(acc[7], dn, b1.w), 0.f);
            *(float4*)&hS[r][ql * 8]     = o0;
            *(float4*)&hS[r][ql * 8 + 4] = o1;
        } else {
            *(float4*)&hS[r][ql * 8]     = make_float4(0.f, 0.f, 0.f, 0.f);
            *(float4*)&hS[r][ql * 8 + 4] = make_float4(0.f, 0.f, 0.f, 0.f);
        }
    }

    // ---- GEMM: h1[128,64] @ conv2W[64,64] ----
    const int lane = tid & 31;
    const int warp = tid >> 5;
    const int g = lane >> 2, tt = lane & 3;
    const int rm = (warp >> 1) * 32;
    const int cn = (warp & 1) * 32;

    float acc[2][4][4];
    #pragma unroll
    for (int a = 0; a < 2; a++)
        #pragma unroll
        for (int b = 0; b < 4; b++)
            #pragma unroll
            for (int c = 0; c < 4; c++) acc[a][b][c] = 0.f;

    for (int k0 = 0; k0 < 64; k0 += 16) {
        __syncthreads();
        {
            int k  = tid >> 4;
            int nq = (tid & 15) * 4;
            float4 v = *(const float4*)&conv2W[(size_t)(k0 + k) * H + nq];
            wS[nq + 0][k] = v.x; wS[nq + 1][k] = v.y;
            wS[nq + 2][k] = v.z; wS[nq + 3][k] = v.w;
        }
        __syncthreads();
        run_chunk16(hS, wS, k0, rm, cn, g, tt, acc);
    }

    #pragma unroll
    for (int nt = 0; nt < 4; nt++) {
        int col = cn + nt * 8 + 2 * tt;
        #pragma unroll
        for (int mt = 0; mt < 2; mt++) {
            int r0 = rowBase + rm + mt * 16 + g;
            int r1 = r0 + 8;
            if (r0 < M) hw2[(size_t)r0 * 32 + (col >> 1)] =
                __floats2half2_rn(acc[mt][nt][0], acc[mt][nt][1]);
            if (r1 < M) hw2[(size_t)r1 * 32 + (col >> 1)] =
                __floats2half2_rn(acc[mt][nt][2], acc[mt][nt][3]);
        }
    }
}

// ---------------------------------------------------------------------------
// Standalone aggregation (layer 2): h2 = relu(Âhw2 + b2) -> fp32 d_out.
// Quarter-warp layout, 4-way split per node, shfl combine. (R13 structure.)
// ---------------------------------------------------------------------------
__global__ void __launch_bounds__(256)
aggregate_h(const uint4* __restrict__ hwH4, const int* __restrict__ ptr,
            const int* __restrict__ cnt, const int* __restrict__ srow,
            const float* __restrict__ wrow, const float* __restrict__ dinv,
            const float* __restrict__ bias, float* __restrict__ out, int n) {
    int warpId = (blockIdx.x * blockDim.x + threadIdx.x) >> 5;
    if (warpId >= n) return;
    int lane = threadIdx.x & 31;
    int qi = lane >> 3, ql = lane & 7;
    int nd = warpId;
    float dn = dinv[nd];
    int st = ptr[nd], c = cnt[nd];
    cudaGridDependencySynchronize();   // PDL: hwH produced by upstream kernel

    int q = c >> 2, rmd = c & 3;
    int beg = st + qi * q + min(qi, rmd);
    int end = beg + q + (qi < rmd ? 1 : 0);

    float acc[8] = {0.f, 0.f, 0.f, 0.f, 0.f, 0.f, 0.f, 0.f};
    if (qi == 0)
        accH(acc, hwH4[(size_t)nd * 8 + ql], dn);          // self loop

    int i = beg;
    for (; i + 2 <= end; i += 2) {
        int r0 = srow[i], r1 = srow[i + 1];
        float w0 = wrow[i], w1 = wrow[i + 1];
        uint4 v0 = hwH4[(size_t)r0 * 8 + ql];
        uint4 v1 = hwH4[(size_t)r1 * 8 + ql];
        accH(acc, v0, w0);
        accH(acc, v1, w1);
    }
    if (i < end)
        accH(acc, hwH4[(size_t)srow[i] * 8 + ql], wrow[i]);

    #pragma unroll
    for (int k = 0; k < 8; k++) {
        acc[k] += __shfl_xor_sync(0xffffffffu, acc[k], 8);
        acc[k] += __shfl_xor_sync(0xffffffffu, acc[k], 16);
    }
    if (qi == 0) {
        float4 b0 = ((const float4*)bias)[ql * 2];
        float4 b1 = ((const float4*)bias)[ql * 2 + 1];
        float4 o0, o1;
        o0.x = fmaxf(fmaf(acc[0], dn, b0.x), 0.f);
        o0.y = fmaxf(fmaf(acc[1], dn, b0.y), 0.f);
        o0.z = fmaxf(fmaf(acc[2], dn, b0.z), 0.f);
        o0.w = fmaxf(fmaf(acc[3], dn, b0.w), 0.f);
        o1.x = fmaxf(fmaf(acc[4], dn, b1.x), 0.f);
        o1.y = fmaxf(fmaf(acc[5], dn, b1.y), 0.f);
        o1.z = fmaxf(fmaf(acc[6], dn, b1.z), 0.f);
        o1.w = fmaxf(fmaf(acc[7], dn, b1.w), 0.f);
        *(float4*)&out[(size_t)nd * H + ql * 8]     = o0;
        *(float4*)&out[(size_t)nd * H + ql * 8 + 4] = o1;
    }
}

// ---------------------------------------------------------------------------
// Fused Pr|Pc GEMM -> packed fp16 outputs for the edge phase:
//   PrH = half2(h2 @ (Wr*s)),  PcH = half2(h2 @ (Wc*s) + t)
// (Standalone, R13 structure — runs after aggregate_h completes, so
//  overwriting bufA/bufB here is safe.)
// ---------------------------------------------------------------------------
__global__ void __launch_bounds__(256)
gemm_pq(const float* __restrict__ A, const float* __restrict__ W,
        const float* __restrict__ s, const float* __restrict__ t,
        __half2* __restrict__ PrH, __half2* __restrict__ PcH, int M) {
    cudaGridDependencySynchronize();
    __shared__ float aS[128][68];     // h2 tile fp32 (staged once, K=64)
    __shared__ float wS[128][20];     // W' chunk [n][k], fp32

    const int tid  = threadIdx.x;
    const int lane = tid & 31;
    const int warp = tid >> 5;
    const int g = lane >> 2, tt = lane & 3;
    const int rm = (warp >> 2) * 64;          // 0 or 64
    const int cn = (warp & 3) * 32;           // 0,32,64,96
    const int rowBase = blockIdx.x * GTM;

    // stage full A tile (K=64) once
    #pragma unroll
    for (int it = 0; it < 8; it++) {
        int li = tid + it * 256;              // 0..2047 (128 rows x 16 float4)
        int r  = li >> 4;
        int kq = (li & 15) * 4;
        int gr = rowBase + r;
        float4 v = make_float4(0.f, 0.f, 0.f, 0.f);
        if (gr < M) v = *(const float4*)&A[(size_t)gr * 64 + kq];
        *(float4*)&aS[r][kq] = v;
    }

    float acc[4][4][4];
    #pragma unroll
    for (int a = 0; a < 4; a++)
        #pragma unroll
        for (int b = 0; b < 4; b++)
            #pragma unroll
            for (int c = 0; c < 4; c++) acc[a][b][c] = 0.f;

    for (int k0 = 0; k0 < 64; k0 += 16) {
        __syncthreads();
        // stage W' chunk: n<64 from Wr, n>=64 from Wc; scale by s[n%64]
        #pragma unroll
        for (int hh = 0; hh < 2; hh++) {
            int k  = tid >> 4;
            int nq = (tid & 15) * 4;
            float4 v = *(const float4*)&W[(size_t)(hh * 64 + k0 + k) * 64 + nq];
            float4 sc = *(const float4*)&s[nq];
            int nb = hh * 64 + nq;
            wS[nb + 0][k] = v.x * sc.x; wS[nb + 1][k] = v.y * sc.y;
            wS[nb + 2][k] = v.z * sc.z; wS[nb + 3][k] = v.w * sc.w;
        }
        __syncthreads();

        #pragma unroll
        for (int kk = 0; kk < 16; kk += 8) {
            unsigned ah[4][4], al[4][4];
            #pragma unroll
            for (int mt = 0; mt < 4; mt++) {
                int rb = rm + mt * 16;
                float a0 = aS[rb + g    ][k0 + kk + tt];
                float a1 = aS[rb + g + 8][k0 + kk + tt];
                float a2 = aS[rb + g    ][k0 + kk + tt + 4];
                float a3 = aS[rb + g + 8][k0 + kk + tt + 4];
                split_tf32(a0, ah[mt][0], al[mt][0]);
                split_tf32(a1, ah[mt][1], al[mt][1]);
                split_tf32(a2, ah[mt][2], al[mt][2]);
                split_tf32(a3, ah[mt][3], al[mt][3]);
            }
            #pragma unroll
            for (int nt = 0; nt < 4; nt++) {
                int cb = cn + nt * 8;
                float b0 = wS[cb + g][kk + tt];
                float b1 = wS[cb + g][kk + tt + 4];
                unsigned bh0, bl0, bh1, bl1;
                split_tf32(b0, bh0, bl0);
                split_tf32(b1, bh1, bl1);
                #pragma unroll
                for (int mt = 0; mt < 4; mt++) {
                    mma_tf32(acc[mt][nt], ah[mt][0], ah[mt][1], ah[mt][2], ah[mt][3], bh0, bh1);
                    mma_tf32(acc[mt][nt], al[mt][0], al[mt][1], al[mt][2], al[mt][3], bh0, bh1);
                    mma_tf32(acc[mt][nt], ah[mt][0], ah[mt][1], ah[mt][2], ah[mt][3], bl0, bl1);
                }
            }
        }
    }

    // epilogue: n<64 -> PrH, n>=64 -> PcH (+t), packed half2
    bool isPc = (cn >= 64);
    __half2* dst = isPc ? PcH : PrH;
    int cbase = isPc ? (cn - 64) : cn;
    #pragma unroll
    for (int mt = 0; mt < 4; mt++) {
        #pragma unroll
        for (int nt = 0; nt < 4; nt++) {
            int col = cbase + nt * 8 + 2 * tt;
            float a0 = 0.f, a1 = 0.f;
            if (isPc) { a0 = t[col]; a1 = t[col + 1]; }
            float v0 = acc[mt][nt][0] + a0, v1 = acc[mt][nt][1] + a1;
            float v2 = acc[mt][nt][2] + a0, v3 = acc[mt][nt][3] + a1;
            int r0 = rowBase + rm + mt * 16 + g;
            int r1 = r0 + 8;
            if (r0 < M) dst[(size_t)r0 * 32 + (col >> 1)] = __floats2half2_rn(v0, v1);
            if (r1 < M) dst[(size_t)r1 * 32 + (col >> 1)] = __floats2half2_rn(v2, v3);
        }
    }
}

// ---------------------------------------------------------------------------
// CSR-ordered edge predictor (NEW R16): one 8-lane group per destination node.
// Pc[c] loaded ONCE per node (sequential); only Pr[srow[i]] is a random
// gather. Halves random 128B-gather traffic vs per-edge order.
//   z = relu(PrH[r] + PcH[c]);  out[eid[i]] = sigmoid(dot(z, w2) + b2)
// ---------------------------------------------------------------------------
__global__ void __launch_bounds__(256)
edge_csr_kernel(const uint4* __restrict__ PrH4, const uint4* __restrict__ PcH4,
                const int* __restrict__ ptr, const int* __restrict__ cnt,
                const int* __restrict__ srow, const int* __restrict__ eid,
                const float* __restrict__ w2, const float* __restrict__ b2,
                float* __restrict__ out, int n) {
    cudaGridDependencySynchronize();   // PDL: PrH/PcH produced by gemm_pq
    int gid = (blockIdx.x * blockDim.x + threadIdx.x) >> 3;
    int ql = threadIdx.x & 7;
    if (gid >= n) return;

    float4 ua = ((const float4*)w2)[ql * 2];
    float4 ub = ((const float4*)w2)[ql * 2 + 1];
    float bb = b2[0];
    const __half2 z2 = __float2half2_rn(0.f);

    int c = gid;
    uint4 pc = PcH4[(size_t)c * 8 + ql];   // one sequential load per node
    int st = ptr[c], num = cnt[c];
    int iend = st + num;

    for (int i = st; i < iend; i += 2) {
        // batch 2 edges for MLP
        int r0 = srow[i];
        int e0 = eid[i];
        uint4 a0 = PrH4[(size_t)r0 * 8 + ql];
        bool has1 = (i + 1 < iend);
        int r1 = has1 ? srow[i + 1] : r0;
        int e1 = has1 ? eid[i + 1] : 0;
        uint4 a1 = PrH4[(size_t)r1 * 8 + ql];

        // edge 0
        {
            __half2 h0 = __hmax2(__hadd2(u2h2(a0.x), u2h2(pc.x)), z2);
            __half2 h1 = __hmax2(__hadd2(u2h2(a0.y), u2h2(pc.y)), z2);
            __half2 h2 = __hmax2(__hadd2(u2h2(a0.z), u2h2(pc.z)), z2);
            __half2 h3 = __hmax2(__hadd2(u2h2(a0.w), u2h2(pc.w)), z2);
            float2 f0 = __half22float2(h0);
            float2 f1 = __half22float2(h1);
            float2 f2 = __half22float2(h2);
            float2 f3 = __half22float2(h3);
            float p = f0.x * ua.x;
            p = fmaf(f0.y, ua.y, p);
            p = fmaf(f1.x, ua.z, p);
            p = fmaf(f1.y, ua.w, p);
            p = fmaf(f2.x, ub.x, p);
            p = fmaf(f2.y, ub.y, p);
            p = fmaf(f3.x, ub.z, p);
            p = fmaf(f3.y, ub.w, p);
            p += __shfl_down_sync(0xffffffffu, p, 4, 8);
            p += __shfl_down_sync(0xffffffffu, p, 2, 8);
            p += __shfl_down_sync(0xffffffffu, p, 1, 8);
            if (ql == 0)
                out[e0] = 1.f / (1.f + __expf(-(p + bb)));
        }
        // edge 1
        if (has1) {
            __half2 h0 = __hmax2(__hadd2(u2h2(a1.x), u2h2(pc.x)), z2);
            __half2 h1 = __hmax2(__hadd2(u2h2(a1.y), u2h2(pc.y)), z2);
            __half2 h2 = __hmax2(__hadd2(u2h2(a1.z), u2h2(pc.z)), z2);
            __half2 h3 = __hmax2(__hadd2(u2h2(a1.w), u2h2(pc.w)), z2);
            float2 f0 = __half22float2(h0);
            float2 f1 = __half22float2(h1);
            float2 f2 = __half22float2(h2);
            float2 f3 = __half22float2(h3);
            float p = f0.x * ua.x;
            p = fmaf(f0.y, ua.y, p);
            p = fmaf(f1.x, ua.z, p);
            p = fmaf(f1.y, ua.w, p);
            p = fmaf(f2.x, ub.x, p);
            p = fmaf(f2.y, ub.y, p);
            p = fmaf(f3.x, ub.z, p);
            p = fmaf(f3.y, ub.w, p);
            p += __shfl_down_sync(0xffffffffu, p, 4, 8);
            p += __shfl_down_sync(0xffffffffu, p, 2, 8);
            p += __shfl_down_sync(0xffffffffu, p, 1, 8);
            if (ql == 0)
                out[e1] = 1.f / (1.f + __expf(-(p + bb)));
        }
    }
}

// ---------------------------------------------------------------------------
// PDL launch helper (programmatic stream serialization; graph-capturable)
// ---------------------------------------------------------------------------
template<typename F, typename... Args>
static void pdl_launch(F kern, dim3 grid, dim3 block, Args... args) {
    cudaLaunchConfig_t cfg = {};
    cfg.gridDim = grid;
    cfg.blockDim = block;
    cfg.dynamicSmemBytes = 0;
    cfg.stream = 0;
    cudaLaunchAttribute at[1];
    at[0].id = cudaLaunchAttributeProgrammaticStreamSerialization;
    at[0].val.programmaticStreamSerializationAllowed = 1;
    cfg.attrs = at;
    cfg.numAttrs = 1;
    cudaLaunchKernelEx(&cfg, kern, args...);
}

// ---------------------------------------------------------------------------
// Launch sequence: side-stream CSR setup overlaps fused_enc_conv1; main chain
// is 5 kernels (R13 structure) with PDL between consecutive stages.
// ---------------------------------------------------------------------------
extern "C" void kernel_launch(void* const* d_in, const int* in_sizes, int n_in,
                              void* d_out, int out_size) {
    const float* x        = (const float*)d_in[0];
    const int*   eidx     = (const int*)  d_in[1];
    const float* enc_W    = (const float*)d_in[2];
    const float* enc_b    = (const float*)d_in[3];
    const float* enc_g    = (const float*)d_in[4];
    const float* enc_beta = (const float*)d_in[5];
    const float* enc_mean = (const float*)d_in[6];
    const float* enc_var  = (const float*)d_in[7];
    const float* conv1_W  = (const float*)d_in[8];
    const float* conv1_b  = (const float*)d_in[9];
    const float* conv2_W  = (const float*)d_in[10];
    const float* conv2_b  = (const float*)d_in[11];
    const float* ep1_W    = (const float*)d_in[12];
    const float* ep1_b    = (const float*)d_in[13];
    const float* ep_g     = (const float*)d_in[14];
    const float* ep_beta  = (const float*)d_in[15];
    const float* ep_mean  = (const float*)d_in[16];
    const float* ep_var   = (const float*)d_in[17];
    const float* ep2_W    = (const float*)d_in[18];
    const float* ep2_b    = (const float*)d_in[19];

    int n = in_sizes[0] / 128;   // nodes
    int e = in_sizes[1] / 2;     // edges
    const int* row = eidx;
    const int* col = eidx + e;
    float* out = (float*)d_out;

    // Resolve scratch symbols (pure lookups; capture-safe)
    float *bufA, *bufB, *dinv, *wrow, *ep_s, *ep_t;
    int *cnt, *fill, *ptr, *srow, *eid, *bsum, *boff;
    cudaGetSymbolAddress((void**)&bufA, g_bufA);
    cudaGetSymbolAddress((void**)&bufB, g_bufB);
    cudaGetSymbolAddress((void**)&cnt,  g_cnt);
    cudaGetSymbolAddress((void**)&fill, g_fill);
    cudaGetSymbolAddress((void**)&ptr,  g_ptr);
    cudaGetSymbolAddress((void**)&srow, g_srow);
    cudaGetSymbolAddress((void**)&wrow, g_wrow);
    cudaGetSymbolAddress((void**)&eid,  g_eid);
    cudaGetSymbolAddress((void**)&dinv, g_dinv);
    cudaGetSymbolAddress((void**)&bsum, g_bsum);
    cudaGetSymbolAddress((void**)&boff, g_boff);
    cudaGetSymbolAddress((void**)&ep_s, g_ep_s);
    cudaGetSymbolAddress((void**)&ep_t, g_ep_t);

    // Side stream + events created once on the (non-captured) correctness call
    static cudaStream_t s2 = nullptr;
    static cudaEvent_t evFork = nullptr, evJoin = nullptr;
    if (s2 == nullptr) {
        cudaStreamCreateWithFlags(&s2, cudaStreamNonBlocking);
        cudaEventCreateWithFlags(&evFork, cudaEventDisableTiming);
        cudaEventCreateWithFlags(&evJoin, cudaEventDisableTiming);
    }

    int nB256 = (n + 255) / 256;
    int eB256 = (e + 255) / 256;
    int nb    = (n + 1023) / 1024;
    int gemmB = (n + GTM - 1) / GTM;

    // --- fork: CSR/degree/BN-fold setup on s2, overlapping fused_enc_conv1 ---
    cudaEventRecord(evFork, 0);
    cudaStreamWaitEvent(s2, evFork, 0);

    zero_kernel<<<nB256, 256, 0, s2>>>(cnt, fill, n);
    prep_consts<<<1, 64, 0, s2>>>(ep1_b, ep_g, ep_beta, ep_mean, ep_var, ep_s, ep_t);
    hist_kernel<<<eB256, 256, 0, s2>>>(col, cnt, e);
    scan1<<<nb, 1024, 0, s2>>>(cnt, ptr, bsum, dinv, n);
    scan2<<<1, 128, 0, s2>>>(bsum, boff, nb);
    scan3<<<nB256, 256, 0, s2>>>(ptr, boff, n);
    fill_kernel<<<eB256, 256, 0, s2>>>(row, col, ptr, fill, srow, wrow, eid, dinv, e);
    cudaEventRecord(evJoin, s2);

    // --- main chain (legacy stream; 5 kernels, R13 structure) ---
    // hw1 = half( relu(bn(x@encW)) @ conv1W )   -> bufA (packed half2)
    pdl_launch(fused_enc_conv1, dim3(gemmB), dim3(256),
               x, enc_W, enc_b, enc_g, enc_beta, enc_mean, enc_var,
               conv1_W, (__half2*)bufA, n);

    // join: aggregation needs ptr/cnt/srow/wrow/dinv
    cudaStreamWaitEvent(0, evJoin, 0);

    // hw2 = half( relu(Â hw1 + b1) @ conv2W )   -> bufB (packed half2)
    pdl_launch(fused_agg_conv2, dim3(gemmB), dim3(256),
               (const uint4*)bufA, (const int*)ptr, (const int*)cnt, (const int*)srow,
               (const float*)wrow, (const float*)dinv, conv1_b, conv2_W,
               (__half2*)bufB, n);

    // h2 = relu(Â hw2 + b2)                      -> d_out[0 : n*64] (fp32 output)
    pdl_launch(aggregate_h, dim3((n * 32 + 255) / 256), dim3(256),
               (const uint4*)bufB, (const int*)ptr, (const int*)cnt, (const int*)srow,
               (const float*)wrow, (const float*)dinv, conv2_b, out, n);

    // [PrH|PcH] = half(h2 @ [Wr*s|Wc*s] (+t))    -> bufA / bufB
    // (runs after aggregate_h's full grid; overwriting bufA/bufB is safe)
    pdl_launch(gemm_pq, dim3(gemmB), dim3(256),
               (const float*)out, ep1_W, (const float*)ep_s, (const float*)ep_t,
               (__half2*)bufA, (__half2*)bufB, n);

    // CSR-ordered edge predictor: Pc loaded once per node, Pr gathered per edge
    pdl_launch(edge_csr_kernel, dim3((n * 8 + 255) / 256), dim3(256),
               (const uint4*)bufA, (const uint4*)bufB,
               (const int*)ptr, (const int*)cnt, (const int*)srow, (const int*)eid,
               ep2_W, ep2_b, out + (size_t)n * H, n);
}

// round 17
// speedup vs baseline: 1.1756x; 1.1756x over previous
#include <cuda_runtime.h>
#include <cuda_bf16.h>
#include <cuda_fp16.h>
#include <math.h>

// Problem-size maxima (compile-time buffer sizing; runtime sizes passed as args)
#define NMAX 100000
#define EMAX 1600000
#define H 64

// ---------------------------------------------------------------------------
// Device scratch (allocation-free rule: __device__ globals)
// ---------------------------------------------------------------------------
__device__ __align__(16) float g_bufA[NMAX * H];   // 25.6 MB (hw1 half2; PrH half2)
__device__ __align__(16) float g_bufB[NMAX * H];   // 25.6 MB (hw2 half2; PcH half2)
__device__ int   g_cnt [NMAX];
__device__ int   g_fill[NMAX];
__device__ int   g_ptr [NMAX];
__device__ int   g_srow[EMAX];                     // 6.4 MB (CSR source row)
__device__ float g_wrow[EMAX];                     // 6.4 MB (pre-gathered dinv[row])
__device__ float g_dinv[NMAX];
__device__ int   g_bsum[256];
__device__ int   g_boff[256];
__device__ __align__(16) float g_ep_s[H], g_ep_t[H];

// ---------------------------------------------------------------------------
// Small setup kernels (side stream)
// ---------------------------------------------------------------------------
__global__ void zero_kernel(int* cnt, int* fill, int n) {
    int i = blockIdx.x * blockDim.x + threadIdx.x;
    if (i < n) { cnt[i] = 0; fill[i] = 0; }
}

// Fold edge-predictor BN (+ ep1 bias) into per-channel scale/shift.
__global__ void prep_consts(const float* __restrict__ ep1_b, const float* __restrict__ ep_g,
                            const float* __restrict__ ep_beta, const float* __restrict__ ep_mean,
                            const float* __restrict__ ep_var,
                            float* ep_s, float* ep_t) {
    int j = threadIdx.x;
    if (j < H) {
        float sp = ep_g[j] * rsqrtf(ep_var[j] + 1e-5f);
        ep_s[j] = sp;
        ep_t[j] = (ep1_b[j] - ep_mean[j]) * sp + ep_beta[j];
    }
}

__global__ void hist_kernel(const int* __restrict__ col, int* cnt, int e) {
    int i = blockIdx.x * blockDim.x + threadIdx.x;
    if (i < e) atomicAdd(&cnt[col[i]], 1);
}

// ---- 3-phase exclusive scan over cnt[] -> ptr[]  (also emits dinv) ----
__global__ void scan1(const int* __restrict__ cnt, int* ptr, int* bsum,
                      float* __restrict__ dinv, int n) {
    __shared__ int sh[1024];
    int t = threadIdx.x;
    int idx = blockIdx.x * 1024 + t;
    int v = (idx < n) ? cnt[idx] : 0;
    if (idx < n) dinv[idx] = rsqrtf((float)(v + 1));   // +1 = self loop; deg >= 1
    sh[t] = v;
    __syncthreads();
    #pragma unroll
    for (int o = 1; o < 1024; o <<= 1) {
        int x = (t >= o) ? sh[t - o] : 0;
        __syncthreads();
        sh[t] += x;
        __syncthreads();
    }
    if (idx < n) ptr[idx] = sh[t] - v;        // exclusive
    if (t == 1023) bsum[blockIdx.x] = sh[t];  // block total
}

__global__ void scan2(const int* __restrict__ bsum, int* boff, int nb) {
    __shared__ int sh[128];
    int t = threadIdx.x;
    int v = (t < nb) ? bsum[t] : 0;
    sh[t] = v;
    __syncthreads();
    #pragma unroll
    for (int o = 1; o < 128; o <<= 1) {
        int x = (t >= o) ? sh[t - o] : 0;
        __syncthreads();
        sh[t] += x;
        __syncthreads();
    }
    if (t < nb) boff[t] = sh[t] - v;          // exclusive
}

__global__ void scan3(int* ptr, const int* __restrict__ boff, int n) {
    int i = blockIdx.x * blockDim.x + threadIdx.x;
    if (i < n) ptr[i] += boff[i >> 10];
}

// CSR fill: bucket edges by destination node (col); also pre-gather edge weight
__global__ void fill_kernel(const int* __restrict__ row, const int* __restrict__ col,
                            const int* __restrict__ ptr, int* fill, int* srow,
                            float* wrow, const float* __restrict__ dinv, int e) {
    int i = blockIdx.x * blockDim.x + threadIdx.x;
    if (i >= e) return;
    int c = col[i];
    int r = row[i];
    int pos = ptr[c] + atomicAdd(&fill[c], 1);
    srow[pos] = r;
    wrow[pos] = dinv[r];
}

// ---------------------------------------------------------------------------
// tf32 helpers. TERM3=true: 3xTF32 split (A*B ~= AhiBhi + AloBhi + AhiBlo).
// TERM3=false: 2-term (AhiBhi + AloBhi) — valid when the GEMM output is
// rounded to fp16 anyway (dropped AhiBlo term ~2^-11, same as fp16 rounding).
// ---------------------------------------------------------------------------
__device__ __forceinline__ unsigned f2tf32(float x) {
    unsigned r;
    asm("cvt.rna.tf32.f32 %0, %1;" : "=r"(r) : "f"(x));
    return r;
}
__device__ __forceinline__ void split_tf32(float x, unsigned& hi, unsigned& lo) {
    hi = f2tf32(x);
    lo = f2tf32(x - __uint_as_float(hi));
}
__device__ __forceinline__ void mma_tf32(float c[4],
                                         unsigned a0, unsigned a1, unsigned a2, unsigned a3,
                                         unsigned b0, unsigned b1) {
    asm volatile("mma.sync.aligned.m16n8k8.row.col.f32.tf32.tf32.f32 "
                 "{%0,%1,%2,%3}, {%4,%5,%6,%7}, {%8,%9}, {%0,%1,%2,%3};"
                 : "+f"(c[0]), "+f"(c[1]), "+f"(c[2]), "+f"(c[3])
                 : "r"(a0), "r"(a1), "r"(a2), "r"(a3), "r"(b0), "r"(b1));
}

#define GTM 128   // rows per block (all node-dim tiles)

// One 16-wide K chunk of the 128x64 tile GEMM (2 kk-steps of m16n8k8).
template<bool TERM3>
__device__ __forceinline__ void run_chunk16(const float (*AS)[68], const float (*WS)[20],
                                            int kbase, int rm, int cn, int g, int tt,
                                            float acc[2][4][4]) {
    #pragma unroll
    for (int kk = 0; kk < 16; kk += 8) {
        unsigned ah[2][4], al[2][4];
        #pragma unroll
        for (int mt = 0; mt < 2; mt++) {
            int rb = rm + mt * 16;
            float a0 = AS[rb + g    ][kbase + kk + tt];
            float a1 = AS[rb + g + 8][kbase + kk + tt];
            float a2 = AS[rb + g    ][kbase + kk + tt + 4];
            float a3 = AS[rb + g + 8][kbase + kk + tt + 4];
            split_tf32(a0, ah[mt][0], al[mt][0]);
            split_tf32(a1, ah[mt][1], al[mt][1]);
            split_tf32(a2, ah[mt][2], al[mt][2]);
            split_tf32(a3, ah[mt][3], al[mt][3]);
        }
        #pragma unroll
        for (int nt = 0; nt < 4; nt++) {
            int cb = cn + nt * 8;
            float b0 = WS[cb + g][kk + tt];
            float b1 = WS[cb + g][kk + tt + 4];
            if (TERM3) {
                unsigned bh0, bl0, bh1, bl1;
                split_tf32(b0, bh0, bl0);
                split_tf32(b1, bh1, bl1);
                #pragma unroll
                for (int mt = 0; mt < 2; mt++) {
                    mma_tf32(acc[mt][nt], ah[mt][0], ah[mt][1], ah[mt][2], ah[mt][3], bh0, bh1);
                    mma_tf32(acc[mt][nt], al[mt][0], al[mt][1], al[mt][2], al[mt][3], bh0, bh1);
                    mma_tf32(acc[mt][nt], ah[mt][0], ah[mt][1], ah[mt][2], ah[mt][3], bl0, bl1);
                }
            } else {
                unsigned bh0 = f2tf32(b0);
                unsigned bh1 = f2tf32(b1);
                #pragma unroll
                for (int mt = 0; mt < 2; mt++) {
                    mma_tf32(acc[mt][nt], ah[mt][0], ah[mt][1], ah[mt][2], ah[mt][3], bh0, bh1);
                    mma_tf32(acc[mt][nt], al[mt][0], al[mt][1], al[mt][2], al[mt][3], bh0, bh1);
                }
            }
        }
    }
}

// ---------------------------------------------------------------------------
// Fused encoder + conv1:  hw1 = half( relu(bn(x@encW + b)) @ conv1W )
// h0 never touches global memory. GEMM1: 3-term (fp32 context);
// GEMM2: 2-term (output is fp16).
// ---------------------------------------------------------------------------
__global__ void __launch_bounds__(256)
fused_enc_conv1(const float* __restrict__ x, const float* __restrict__ encW,
                const float* __restrict__ bn_b, const float* __restrict__ bn_g,
                const float* __restrict__ bn_beta, const float* __restrict__ bn_mean,
                const float* __restrict__ bn_var,
                const float* __restrict__ conv1W,
                __half2* __restrict__ hw1, int M) {
    cudaGridDependencySynchronize();
    __shared__ float wS[64][20];    // W^T chunk (fp32), reused GEMM1+GEMM2
    __shared__ float uS[128][68];   // GEMM1 A-chunks in cols [0..15]; then h0 full

    const int tid  = threadIdx.x;
    const int lane = tid & 31;
    const int warp = tid >> 5;
    const int g = lane >> 2, tt = lane & 3;
    const int rm = (warp >> 1) * 32;
    const int cn = (warp & 1) * 32;
    const int rowBase = blockIdx.x * GTM;

    float acc[2][4][4];
    #pragma unroll
    for (int a = 0; a < 2; a++)
        #pragma unroll
        for (int b = 0; b < 4; b++)
            #pragma unroll
            for (int c = 0; c < 4; c++) acc[a][b][c] = 0.f;

    // ---- GEMM1: x[M,128] @ encW[128,64]  (3-term) ----
    for (int k0 = 0; k0 < 128; k0 += 16) {
        __syncthreads();
        #pragma unroll
        for (int it = 0; it < 2; it++) {
            int li = tid + it * 256;
            int r  = li >> 2;
            int kq = (li & 3) * 4;
            int gr = rowBase + r;
            float4 v = make_float4(0.f, 0.f, 0.f, 0.f);
            if (gr < M) v = *(const float4*)&x[(size_t)gr * 128 + k0 + kq];
            *(float4*)&uS[r][kq] = v;
        }
        {
            int k  = tid >> 4;
            int nq = (tid & 15) * 4;
            float4 v = *(const float4*)&encW[(size_t)(k0 + k) * H + nq];
            wS[nq + 0][k] = v.x; wS[nq + 1][k] = v.y;
            wS[nq + 2][k] = v.z; wS[nq + 3][k] = v.w;
        }
        __syncthreads();
        run_chunk16<true>(uS, wS, 0, rm, cn, g, tt, acc);
    }

    // ---- epilogue 1: BN + ReLU -> h0 into uS (full [128][64]) ----
    __syncthreads();
    #pragma unroll
    for (int nt = 0; nt < 4; nt++) {
        int col = cn + nt * 8 + 2 * tt;
        float s0 = bn_g[col]     * rsqrtf(bn_var[col]     + 1e-5f);
        float s1 = bn_g[col + 1] * rsqrtf(bn_var[col + 1] + 1e-5f);
        float t0 = (bn_b[col]     - bn_mean[col])     * s0 + bn_beta[col];
        float t1 = (bn_b[col + 1] - bn_mean[col + 1]) * s1 + bn_beta[col + 1];
        #pragma unroll
        for (int mt = 0; mt < 2; mt++) {
            int r0 = rm + mt * 16 + g;
            int r1 = r0 + 8;
            *(float2*)&uS[r0][col] = make_float2(
                fmaxf(fmaf(acc[mt][nt][0], s0, t0), 0.f),
                fmaxf(fmaf(acc[mt][nt][1], s1, t1), 0.f));
            *(float2*)&uS[r1][col] = make_float2(
                fmaxf(fmaf(acc[mt][nt][2], s0, t0), 0.f),
                fmaxf(fmaf(acc[mt][nt][3], s1, t1), 0.f));
        }
    }

    // ---- GEMM2: h0[128,64] @ conv1W[64,64]  (2-term; output is fp16) ----
    #pragma unroll
    for (int a = 0; a < 2; a++)
        #pragma unroll
        for (int b = 0; b < 4; b++)
            #pragma unroll
            for (int c = 0; c < 4; c++) acc[a][b][c] = 0.f;

    for (int k0 = 0; k0 < 64; k0 += 16) {
        __syncthreads();
        {
            int k  = tid >> 4;
            int nq = (tid & 15) * 4;
            float4 v = *(const float4*)&conv1W[(size_t)(k0 + k) * H + nq];
            wS[nq + 0][k] = v.x; wS[nq + 1][k] = v.y;
            wS[nq + 2][k] = v.z; wS[nq + 3][k] = v.w;
        }
        __syncthreads();
        run_chunk16<false>(uS, wS, k0, rm, cn, g, tt, acc);
    }

    // ---- epilogue 2: hw1 (packed half2) ----
    #pragma unroll
    for (int nt = 0; nt < 4; nt++) {
        int col = cn + nt * 8 + 2 * tt;
        #pragma unroll
        for (int mt = 0; mt < 2; mt++) {
            int r0 = rowBase + rm + mt * 16 + g;
            int r1 = r0 + 8;
            if (r0 < M) hw1[(size_t)r0 * 32 + (col >> 1)] =
                __floats2half2_rn(acc[mt][nt][0], acc[mt][nt][1]);
            if (r1 < M) hw1[(size_t)r1 * 32 + (col >> 1)] =
                __floats2half2_rn(acc[mt][nt][2], acc[mt][nt][3]);
        }
    }
}

// ---------------------------------------------------------------------------
// fp16 gather helpers
// ---------------------------------------------------------------------------
__device__ __forceinline__ __half2 u2h2(unsigned u) {
    __half2 h; *(unsigned*)&h = u; return h;
}
__device__ __forceinline__ void accH(float* acc, uint4 v, float w) {
    float2 f;
    f = __half22float2(u2h2(v.x)); acc[0] = fmaf(f.x, w, acc[0]); acc[1] = fmaf(f.y, w, acc[1]);
    f = __half22float2(u2h2(v.y)); acc[2] = fmaf(f.x, w, acc[2]); acc[3] = fmaf(f.y, w, acc[3]);
    f = __half22float2(u2h2(v.z)); acc[4] = fmaf(f.x, w, acc[4]); acc[5] = fmaf(f.y, w, acc[5]);
    f = __half22float2(u2h2(v.w)); acc[6] = fmaf(f.x, w, acc[6]); acc[7] = fmaf(f.y, w, acc[7]);
}

// ---------------------------------------------------------------------------
// Fused aggregate(hw1) + conv2:  hw2 = half( relu(Âhw1 + b1) @ conv2W )
// h1 lives only in smem. GEMM is 2-term (output is fp16).
// ---------------------------------------------------------------------------
__global__ void __launch_bounds__(256)
fused_agg_conv2(const uint4* __restrict__ hwH4, const int* __restrict__ ptr,
                const int* __restrict__ cnt, const int* __restrict__ srow,
                const float* __restrict__ wrow, const float* __restrict__ dinv,
                const float* __restrict__ bias, const float* __restrict__ conv2W,
                __half2* __restrict__ hw2, int M) {
    cudaGridDependencySynchronize();   // hw1 produced by fused_enc_conv1
    __shared__ float wS[64][20];
    __shared__ float hS[128][68];

    const int tid  = threadIdx.x;
    const int qg = tid >> 3, ql = tid & 7;
    const int rowBase = blockIdx.x * GTM;

    float4 b0 = ((const float4*)bias)[ql * 2];
    float4 b1 = ((const float4*)bias)[ql * 2 + 1];

    // ---- aggregation phase: 32 groups x 4 nodes ----
    #pragma unroll 1
    for (int j = 0; j < 4; j++) {
        int r  = qg * 4 + j;
        int nd = rowBase + r;
        if (nd < M) {
            float dn = dinv[nd];
            int st = ptr[nd], c = cnt[nd];
            float acc[8] = {0.f, 0.f, 0.f, 0.f, 0.f, 0.f, 0.f, 0.f};
            accH(acc, hwH4[(size_t)nd * 8 + ql], dn);      // self loop
            int i = st, iend = st + c;
            for (; i + 4 <= iend; i += 4) {
                int r0 = srow[i], r1 = srow[i + 1], r2 = srow[i + 2], r3 = srow[i + 3];
                float w0 = wrow[i], w1 = wrow[i + 1], w2 = wrow[i + 2], w3 = wrow[i + 3];
                uint4 v0 = hwH4[(size_t)r0 * 8 + ql];
                uint4 v1 = hwH4[(size_t)r1 * 8 + ql];
                uint4 v2 = hwH4[(size_t)r2 * 8 + ql];
                uint4 v3 = hwH4[(size_t)r3 * 8 + ql];
                accH(acc, v0, w0); accH(acc, v1, w1);
                accH(acc, v2, w2); accH(acc, v3, w3);
            }
            for (; i < iend; i++)
                accH(acc, hwH4[(size_t)srow[i] * 8 + ql], wrow[i]);

            float4 o0, o1;
            o0.x = fmaxf(fmaf(acc[0], dn, b0.x), 0.f);
            o0.y = fmaxf(fmaf(acc[1], dn, b0.y), 0.f);
            o0.z = fmaxf(fmaf(acc[2], dn, b0.z), 0.f);
            o0.w = fmaxf(fmaf(acc[3], dn, b0.w), 0.f);
            o1.x = fmaxf(fmaf(acc[4], dn, b1.x), 0.f);
            o1.y = fmaxf(fmaf(acc[5], dn, b1.y), 0.f);
            o1.z = fmaxf(fmaf(acc[6], dn, b1.z), 0.f);
            o1.w = fmaxf(fmaf(acc[7], dn, b1.w), 0.f);
            *(float4*)&hS[r][ql * 8]     = o0;
            *(float4*)&hS[r][ql * 8 + 4] = o1;
        } else {
            *(float4*)&hS[r][ql * 8]     = make_float4(0.f, 0.f, 0.f, 0.f);
            *(float4*)&hS[r][ql * 8 + 4] = make_float4(0.f, 0.f, 0.f, 0.f);
        }
    }

    // ---- GEMM: h1[128,64] @ conv2W[64,64]  (2-term) ----
    const int lane = tid & 31;
    const int warp = tid >> 5;
    const int g = lane >> 2, tt = lane & 3;
    const int rm = (warp >> 1) * 32;
    const int cn = (warp & 1) * 32;

    float acc[2][4][4];
    #pragma unroll
    for (int a = 0; a < 2; a++)
        #pragma unroll
        for (int b = 0; b < 4; b++)
            #pragma unroll
            for (int c = 0; c < 4; c++) acc[a][b][c] = 0.f;

    for (int k0 = 0; k0 < 64; k0 += 16) {
        __syncthreads();
        {
            int k  = tid >> 4;
            int nq = (tid & 15) * 4;
            float4 v = *(const float4*)&conv2W[(size_t)(k0 + k) * H + nq];
            wS[nq + 0][k] = v.x; wS[nq + 1][k] = v.y;
            wS[nq + 2][k] = v.z; wS[nq + 3][k] = v.w;
        }
        __syncthreads();
        run_chunk16<false>(hS, wS, k0, rm, cn, g, tt, acc);
    }

    #pragma unroll
    for (int nt = 0; nt < 4; nt++) {
        int col = cn + nt * 8 + 2 * tt;
        #pragma unroll
        for (int mt = 0; mt < 2; mt++) {
            int r0 = rowBase + rm + mt * 16 + g;
            int r1 = r0 + 8;
            if (r0 < M) hw2[(size_t)r0 * 32 + (col >> 1)] =
                __floats2half2_rn(acc[mt][nt][0], acc[mt][nt][1]);
            if (r1 < M) hw2[(size_t)r1 * 32 + (col >> 1)] =
                __floats2half2_rn(acc[mt][nt][2], acc[mt][nt][3]);
        }
    }
}

// ---------------------------------------------------------------------------
// Standalone aggregation (layer 2): h2 = relu(Âhw2 + b2) -> fp32 d_out.
// Quarter-warp layout, 4-way split per node, shfl combine. (R13 structure.)
// ---------------------------------------------------------------------------
__global__ void __launch_bounds__(256)
aggregate_h(const uint4* __restrict__ hwH4, const int* __restrict__ ptr,
            const int* __restrict__ cnt, const int* __restrict__ srow,
            const float* __restrict__ wrow, const float* __restrict__ dinv,
            const float* __restrict__ bias, float* __restrict__ out, int n) {
    int warpId = (blockIdx.x * blockDim.x + threadIdx.x) >> 5;
    if (warpId >= n) return;
    int lane = threadIdx.x & 31;
    int qi = lane >> 3, ql = lane & 7;
    int nd = warpId;
    float dn = dinv[nd];
    int st = ptr[nd], c = cnt[nd];
    cudaGridDependencySynchronize();   // PDL: hwH produced by upstream kernel

    int q = c >> 2, rmd = c & 3;
    int beg = st + qi * q + min(qi, rmd);
    int end = beg + q + (qi < rmd ? 1 : 0);

    float acc[8] = {0.f, 0.f, 0.f, 0.f, 0.f, 0.f, 0.f, 0.f};
    if (qi == 0)
        accH(acc, hwH4[(size_t)nd * 8 + ql], dn);          // self loop

    int i = beg;
    for (; i + 2 <= end; i += 2) {
        int r0 = srow[i], r1 = srow[i + 1];
        float w0 = wrow[i], w1 = wrow[i + 1];
        uint4 v0 = hwH4[(size_t)r0 * 8 + ql];
        uint4 v1 = hwH4[(size_t)r1 * 8 + ql];
        accH(acc, v0, w0);
        accH(acc, v1, w1);
    }
    if (i < end)
        accH(acc, hwH4[(size_t)srow[i] * 8 + ql], wrow[i]);

    #pragma unroll
    for (int k = 0; k < 8; k++) {
        acc[k] += __shfl_xor_sync(0xffffffffu, acc[k], 8);
        acc[k] += __shfl_xor_sync(0xffffffffu, acc[k], 16);
    }
    if (qi == 0) {
        float4 b0 = ((const float4*)bias)[ql * 2];
        float4 b1 = ((const float4*)bias)[ql * 2 + 1];
        float4 o0, o1;
        o0.x = fmaxf(fmaf(acc[0], dn, b0.x), 0.f);
        o0.y = fmaxf(fmaf(acc[1], dn, b0.y), 0.f);
        o0.z = fmaxf(fmaf(acc[2], dn, b0.z), 0.f);
        o0.w = fmaxf(fmaf(acc[3], dn, b0.w), 0.f);
        o1.x = fmaxf(fmaf(acc[4], dn, b1.x), 0.f);
        o1.y = fmaxf(fmaf(acc[5], dn, b1.y), 0.f);
        o1.z = fmaxf(fmaf(acc[6], dn, b1.z), 0.f);
        o1.w = fmaxf(fmaf(acc[7], dn, b1.w), 0.f);
        *(float4*)&out[(size_t)nd * H + ql * 8]     = o0;
        *(float4*)&out[(size_t)nd * H + ql * 8 + 4] = o1;
    }
}

// ---------------------------------------------------------------------------
// Fused Pr|Pc GEMM -> packed fp16 outputs for the edge phase:
//   PrH = half2(h2 @ (Wr*s)),  PcH = half2(h2 @ (Wc*s) + t)
// 2-term split (output is fp16). Runs after aggregate_h completes, so
// overwriting bufA/bufB here is safe.
// ---------------------------------------------------------------------------
__global__ void __launch_bounds__(256)
gemm_pq(const float* __restrict__ A, const float* __restrict__ W,
        const float* __restrict__ s, const float* __restrict__ t,
        __half2* __restrict__ PrH, __half2* __restrict__ PcH, int M) {
    cudaGridDependencySynchronize();
    __shared__ float aS[128][68];     // h2 tile fp32 (staged once, K=64)
    __shared__ float wS[128][20];     // W' chunk [n][k], fp32

    const int tid  = threadIdx.x;
    const int lane = tid & 31;
    const int warp = tid >> 5;
    const int g = lane >> 2, tt = lane & 3;
    const int rm = (warp >> 2) * 64;          // 0 or 64
    const int cn = (warp & 3) * 32;           // 0,32,64,96
    const int rowBase = blockIdx.x * GTM;

    // stage full A tile (K=64) once
    #pragma unroll
    for (int it = 0; it < 8; it++) {
        int li = tid + it * 256;              // 0..2047 (128 rows x 16 float4)
        int r  = li >> 4;
        int kq = (li & 15) * 4;
        int gr = rowBase + r;
        float4 v = make_float4(0.f, 0.f, 0.f, 0.f);
        if (gr < M) v = *(const float4*)&A[(size_t)gr * 64 + kq];
        *(float4*)&aS[r][kq] = v;
    }

    float acc[4][4][4];
    #pragma unroll
    for (int a = 0; a < 4; a++)
        #pragma unroll
        for (int b = 0; b < 4; b++)
            #pragma unroll
            for (int c = 0; c < 4; c++) acc[a][b][c] = 0.f;

    for (int k0 = 0; k0 < 64; k0 += 16) {
        __syncthreads();
        // stage W' chunk: n<64 from Wr, n>=64 from Wc; scale by s[n%64]
        #pragma unroll
        for (int hh = 0; hh < 2; hh++) {
            int k  = tid >> 4;
            int nq = (tid & 15) * 4;
            float4 v = *(const float4*)&W[(size_t)(hh * 64 + k0 + k) * 64 + nq];
            float4 sc = *(const float4*)&s[nq];
            int nb = hh * 64 + nq;
            wS[nb + 0][k] = v.x * sc.x; wS[nb + 1][k] = v.y * sc.y;
            wS[nb + 2][k] = v.z * sc.z; wS[nb + 3][k] = v.w * sc.w;
        }
        __syncthreads();

        #pragma unroll
        for (int kk = 0; kk < 16; kk += 8) {
            unsigned ah[4][4], al[4][4];
            #pragma unroll
            for (int mt = 0; mt < 4; mt++) {
                int rb = rm + mt * 16;
                float a0 = aS[rb + g    ][k0 + kk + tt];
                float a1 = aS[rb + g + 8][k0 + kk + tt];
                float a2 = aS[rb + g    ][k0 + kk + tt + 4];
                float a3 = aS[rb + g + 8][k0 + kk + tt + 4];
                split_tf32(a0, ah[mt][0], al[mt][0]);
                split_tf32(a1, ah[mt][1], al[mt][1]);
                split_tf32(a2, ah[mt][2], al[mt][2]);
                split_tf32(a3, ah[mt][3], al[mt][3]);
            }
            #pragma unroll
            for (int nt = 0; nt < 4; nt++) {
                int cb = cn + nt * 8;
                unsigned bh0 = f2tf32(wS[cb + g][kk + tt]);
                unsigned bh1 = f2tf32(wS[cb + g][kk + tt + 4]);
                #pragma unroll
                for (int mt = 0; mt < 4; mt++) {
                    mma_tf32(acc[mt][nt], ah[mt][0], ah[mt][1], ah[mt][2], ah[mt][3], bh0, bh1);
                    mma_tf32(acc[mt][nt], al[mt][0], al[mt][1], al[mt][2], al[mt][3], bh0, bh1);
                }
            }
        }
    }

    // epilogue: n<64 -> PrH, n>=64 -> PcH (+t), packed half2
    bool isPc = (cn >= 64);
    __half2* dst = isPc ? PcH : PrH;
    int cbase = isPc ? (cn - 64) : cn;
    #pragma unroll
    for (int mt = 0; mt < 4; mt++) {
        #pragma unroll
        for (int nt = 0; nt < 4; nt++) {
            int col = cbase + nt * 8 + 2 * tt;
            float a0 = 0.f, a1 = 0.f;
            if (isPc) { a0 = t[col]; a1 = t[col + 1]; }
            float v0 = acc[mt][nt][0] + a0, v1 = acc[mt][nt][1] + a1;
            float v2 = acc[mt][nt][2] + a0, v3 = acc[mt][nt][3] + a1;
            int r0 = rowBase + rm + mt * 16 + g;
            int r1 = r0 + 8;
            if (r0 < M) dst[(size_t)r0 * 32 + (col >> 1)] = __floats2half2_rn(v0, v1);
            if (r1 < M) dst[(size_t)r1 * 32 + (col >> 1)] = __floats2half2_rn(v2, v3);
        }
    }
}

// ---------------------------------------------------------------------------
// Edge predictor on fp16 rows (R13 per-edge form — parallelism-preserving):
// 4 edges per warp (one per 8-lane quarter).
//   z = relu(PrH[row] + PcH[col]);  pred = sigmoid(dot(z, w2) + b2)  (fp32 dot)
// ---------------------------------------------------------------------------
__global__ void __launch_bounds__(256)
edge_kernel(const uint4* __restrict__ PrH4, const uint4* __restrict__ PcH4,
            const int* __restrict__ row, const int* __restrict__ col,
            const float* __restrict__ w2, const float* __restrict__ b2,
            float* __restrict__ out, int e) {
    int lane = threadIdx.x & 31;
    int qi = lane >> 3, ql = lane & 7;
    int warp = (blockIdx.x * blockDim.x + threadIdx.x) >> 5;
    int nwarps = (gridDim.x * blockDim.x) >> 5;

    float4 ua = ((const float4*)w2)[ql * 2];
    float4 ub = ((const float4*)w2)[ql * 2 + 1];
    float bb = b2[0];
    const __half2 z2 = __float2half2_rn(0.f);
    cudaGridDependencySynchronize();   // PDL: PrH/PcH produced by gemm_pq

    for (int ei = warp * 4 + qi; ei < e; ei += nwarps * 4) {
        int r = row[ei], c = col[ei];
        uint4 a = PrH4[(size_t)r * 8 + ql];
        uint4 b = PcH4[(size_t)c * 8 + ql];
        __half2 h0 = __hmax2(__hadd2(u2h2(a.x), u2h2(b.x)), z2);
        __half2 h1 = __hmax2(__hadd2(u2h2(a.y), u2h2(b.y)), z2);
        __half2 h2 = __hmax2(__hadd2(u2h2(a.z), u2h2(b.z)), z2);
        __half2 h3 = __hmax2(__hadd2(u2h2(a.w), u2h2(b.w)), z2);
        float2 f0 = __half22float2(h0);
        float2 f1 = __half22float2(h1);
        float2 f2 = __half22float2(h2);
        float2 f3 = __half22float2(h3);
        float p = f0.x * ua.x;
        p = fmaf(f0.y, ua.y, p);
        p = fmaf(f1.x, ua.z, p);
        p = fmaf(f1.y, ua.w, p);
        p = fmaf(f2.x, ub.x, p);
        p = fmaf(f2.y, ub.y, p);
        p = fmaf(f3.x, ub.z, p);
        p = fmaf(f3.y, ub.w, p);
        p += __shfl_down_sync(0xffffffffu, p, 4, 8);
        p += __shfl_down_sync(0xffffffffu, p, 2, 8);
        p += __shfl_down_sync(0xffffffffu, p, 1, 8);
        if (ql == 0)
            out[ei] = 1.f / (1.f + __expf(-(p + bb)));
    }
}

// ---------------------------------------------------------------------------
// PDL launch helper (programmatic stream serialization; graph-capturable)
// ---------------------------------------------------------------------------
template<typename F, typename... Args>
static void pdl_launch(F kern, dim3 grid, dim3 block, Args... args) {
    cudaLaunchConfig_t cfg = {};
    cfg.gridDim = grid;
    cfg.blockDim = block;
    cfg.dynamicSmemBytes = 0;
    cfg.stream = 0;
    cudaLaunchAttribute at[1];
    at[0].id = cudaLaunchAttributeProgrammaticStreamSerialization;
    at[0].val.programmaticStreamSerializationAllowed = 1;
    cfg.attrs = at;
    cfg.numAttrs = 1;
    cudaLaunchKernelEx(&cfg, kern, args...);
}

// ---------------------------------------------------------------------------
// Launch sequence: side-stream CSR setup overlaps fused_enc_conv1; main chain
// is 5 kernels (R13 structure) with PDL between consecutive stages.
// ---------------------------------------------------------------------------
extern "C" void kernel_launch(void* const* d_in, const int* in_sizes, int n_in,
                              void* d_out, int out_size) {
    const float* x        = (const float*)d_in[0];
    const int*   eidx     = (const int*)  d_in[1];
    const float* enc_W    = (const float*)d_in[2];
    const float* enc_b    = (const float*)d_in[3];
    const float* enc_g    = (const float*)d_in[4];
    const float* enc_beta = (const float*)d_in[5];
    const float* enc_mean = (const float*)d_in[6];
    const float* enc_var  = (const float*)d_in[7];
    const float* conv1_W  = (const float*)d_in[8];
    const float* conv1_b  = (const float*)d_in[9];
    const float* conv2_W  = (const float*)d_in[10];
    const float* conv2_b  = (const float*)d_in[11];
    const float* ep1_W    = (const float*)d_in[12];
    const float* ep1_b    = (const float*)d_in[13];
    const float* ep_g     = (const float*)d_in[14];
    const float* ep_beta  = (const float*)d_in[15];
    const float* ep_mean  = (const float*)d_in[16];
    const float* ep_var   = (const float*)d_in[17];
    const float* ep2_W    = (const float*)d_in[18];
    const float* ep2_b    = (const float*)d_in[19];

    int n = in_sizes[0] / 128;   // nodes
    int e = in_sizes[1] / 2;     // edges
    const int* row = eidx;
    const int* col = eidx + e;
    float* out = (float*)d_out;

    // Resolve scratch symbols (pure lookups; capture-safe)
    float *bufA, *bufB, *dinv, *wrow, *ep_s, *ep_t;
    int *cnt, *fill, *ptr, *srow, *bsum, *boff;
    cudaGetSymbolAddress((void**)&bufA, g_bufA);
    cudaGetSymbolAddress((void**)&bufB, g_bufB);
    cudaGetSymbolAddress((void**)&cnt,  g_cnt);
    cudaGetSymbolAddress((void**)&fill, g_fill);
    cudaGetSymbolAddress((void**)&ptr,  g_ptr);
    cudaGetSymbolAddress((void**)&srow, g_srow);
    cudaGetSymbolAddress((void**)&wrow, g_wrow);
    cudaGetSymbolAddress((void**)&dinv, g_dinv);
    cudaGetSymbolAddress((void**)&bsum, g_bsum);
    cudaGetSymbolAddress((void**)&boff, g_boff);
    cudaGetSymbolAddress((void**)&ep_s, g_ep_s);
    cudaGetSymbolAddress((void**)&ep_t, g_ep_t);

    // Side stream + events created once on the (non-captured) correctness call
    static cudaStream_t s2 = nullptr;
    static cudaEvent_t evFork = nullptr, evJoin = nullptr;
    if (s2 == nullptr) {
        cudaStreamCreateWithFlags(&s2, cudaStreamNonBlocking);
        cudaEventCreateWithFlags(&evFork, cudaEventDisableTiming);
        cudaEventCreateWithFlags(&evJoin, cudaEventDisableTiming);
    }

    int nB256 = (n + 255) / 256;
    int eB256 = (e + 255) / 256;
    int nb    = (n + 1023) / 1024;
    int gemmB = (n + GTM - 1) / GTM;

    // --- fork: CSR/degree/BN-fold setup on s2, overlapping fused_enc_conv1 ---
    cudaEventRecord(evFork, 0);
    cudaStreamWaitEvent(s2, evFork, 0);

    zero_kernel<<<nB256, 256, 0, s2>>>(cnt, fill, n);
    prep_consts<<<1, 64, 0, s2>>>(ep1_b, ep_g, ep_beta, ep_mean, ep_var, ep_s, ep_t);
    hist_kernel<<<eB256, 256, 0, s2>>>(col, cnt, e);
    scan1<<<nb, 1024, 0, s2>>>(cnt, ptr, bsum, dinv, n);
    scan2<<<1, 128, 0, s2>>>(bsum, boff, nb);
    scan3<<<nB256, 256, 0, s2>>>(ptr, boff, n);
    fill_kernel<<<eB256, 256, 0, s2>>>(row, col, ptr, fill, srow, wrow, dinv, e);
    cudaEventRecord(evJoin, s2);

    // --- main chain (legacy stream; 5 kernels, R13 structure) ---
    // hw1 = half( relu(bn(x@encW)) @ conv1W )   -> bufA (packed half2)
    pdl_launch(fused_enc_conv1, dim3(gemmB), dim3(256),
               x, enc_W, enc_b, enc_g, enc_beta, enc_mean, enc_var,
               conv1_W, (__half2*)bufA, n);

    // join: aggregation needs ptr/cnt/srow/wrow/dinv
    cudaStreamWaitEvent(0, evJoin, 0);

    // hw2 = half( relu(Â hw1 + b1) @ conv2W )   -> bufB (packed half2)
    pdl_launch(fused_agg_conv2, dim3(gemmB), dim3(256),
               (const uint4*)bufA, (const int*)ptr, (const int*)cnt, (const int*)srow,
               (const float*)wrow, (const float*)dinv, conv1_b, conv2_W,
               (__half2*)bufB, n);

    // h2 = relu(Â hw2 + b2)                      -> d_out[0 : n*64] (fp32 output)
    pdl_launch(aggregate_h, dim3((n * 32 + 255) / 256), dim3(256),
               (const uint4*)bufB, (const int*)ptr, (const int*)cnt, (const int*)srow,
               (const float*)wrow, (const float*)dinv, conv2_b, out, n);

    // [PrH|PcH] = half(h2 @ [Wr*s|Wc*s] (+t))    -> bufA / bufB
    // (runs after aggregate_h's full grid; overwriting bufA/bufB is safe)
    pdl_launch(gemm_pq, dim3(gemmB), dim3(256),
               (const float*)out, ep1_W, (const float*)ep_s, (const float*)ep_t,
               (__half2*)bufA, (__half2*)bufB, n);

    // pred[e] = sigmoid(dot(relu(PrH[row]+PcH[col]), w2) + b2) -> d_out[n*64 : ]
    pdl_launch(edge_kernel, dim3(1184), dim3(256),
               (const uint4*)bufA, (const uint4*)bufB, row, col,
               ep2_W, ep2_b, out + (size_t)n * H, e);
}